// round 9
// baseline (speedup 1.0000x reference)
#include <cuda_runtime.h>
#include <cstdint>

#define K_DIM      128
#define O_DIM      128
#define CHUNK      64          // rows of x per ring slot
#define THREADS    288         // 8 consumer warps (4 o x 2 m) + 1 producer warp
#define LDS_STRIDE 136         // conflict-free LDS.64 phases
#define NBUF       6           // mbarrier ring depth
#define BUF_FLOATS (CHUNK * LDS_STRIDE)
#define MBAR_OFF   (NBUF * BUF_FLOATS * 4)      // 208896
#define SMEM_BYTES (MBAR_OFF + 128)

// x feeds the tf32 MMA as raw fp32 bits (HW truncates to tf32).
// Mean relative shrink of truncation = 2^-11 * ln2 = 3.38e-4; compensate on W.
#define W_SCALE 1.000338f

__device__ __forceinline__ uint32_t cvt_tf32(float f) {
    uint32_t r;
    asm("cvt.rna.tf32.f32 %0, %1;" : "=r"(r) : "f"(f));
    return r;
}
__device__ __forceinline__ void cp_async16(uint32_t smem_addr, const void* gptr) {
    asm volatile("cp.async.cg.shared.global [%0], [%1], 16;" :: "r"(smem_addr), "l"(gptr));
}
__device__ __forceinline__ void cp_commit() {
    asm volatile("cp.async.commit_group;");
}
__device__ __forceinline__ void mbar_init(uint32_t a, uint32_t cnt) {
    asm volatile("mbarrier.init.shared.b64 [%0], %1;" :: "r"(a), "r"(cnt) : "memory");
}
__device__ __forceinline__ void mbar_arrive(uint32_t a) {
    asm volatile("mbarrier.arrive.shared.b64 _, [%0];" :: "r"(a) : "memory");
}
__device__ __forceinline__ void mbar_wait(uint32_t a, uint32_t parity) {
    uint32_t done;
    asm volatile("{\n\t.reg .pred p;\n\t"
                 "mbarrier.try_wait.parity.acquire.cta.shared::cta.b64 p, [%1], %2;\n\t"
                 "selp.b32 %0, 1, 0, p;\n\t}"
                 : "=r"(done) : "r"(a), "r"(parity) : "memory");
    if (!done) {
        asm volatile("{\n\t.reg .pred P1;\n\t"
                     "W_%=:\n\t"
                     "mbarrier.try_wait.parity.acquire.cta.shared::cta.b64 P1, [%0], %1, 0x989680;\n\t"
                     "@P1 bra.uni D_%=;\n\t"
                     "bra.uni W_%=;\n\t"
                     "D_%=:\n\t}"
                     :: "r"(a), "r"(parity) : "memory");
    }
}

// k-permutation: MMA step s, thread t covers logical k {t, t+4}, mapped to
// physical columns {8s+2t, 8s+2t+1}. Applied to BOTH A (x, smem col) and
// B (W, gmem col) -> GEMM unchanged; A frag = one LDS.64.

__global__ void __launch_bounds__(THREADS, 1)
qlinear_tf32_ws(const float* __restrict__ x,
                const float* __restrict__ W,
                float* __restrict__ out,
                int nrows, int nchunks)
{
    extern __shared__ float smem[];
    const int tid = threadIdx.x;
    const int lane = tid & 31, wid = tid >> 5;
    const uint32_t smem_a = (uint32_t)__cvta_generic_to_shared(smem);
    const uint32_t mb = smem_a + MBAR_OFF;      // full[i]@+8i, empty[i]@+48+8i

    if (tid == 0) {
        #pragma unroll
        for (int i = 0; i < NBUF; i++) {
            mbar_init(mb + i * 8, 1);           // full: 1 producer arrival
            mbar_init(mb + 48 + i * 8, 8);      // empty: 8 consumer-warp arrivals
        }
    }
    __syncthreads();                            // barriers visible (only CTA-wide sync)

    const int c0 = blockIdx.x;
    const int g  = gridDim.x;
    const int P  = (nchunks - 1 - c0) / g + 1;  // chunks this CTA processes (c0<nchunks)

    if (wid == 8) {
        // ================= producer warp =================
        int buf = 0, eph = 1;                   // empty-phase starts flipped
        int pc = 0;
        for (int c = c0; c < nchunks; c += g, pc++) {
            mbar_wait(mb + 48 + buf * 8, (uint32_t)eph);     // backpressure
            const int row0 = c * CHUNK;
            const uint32_t base = smem_a + (uint32_t)(buf * BUF_FLOATS) * 4
                                + (uint32_t)lane * 16;
            #pragma unroll 16
            for (int j = 0; j < CHUNK; j++) {   // lane = float4 column, j = row
                int gr = row0 + j;
                if (gr >= nrows) gr = nrows - 1;            // clamp, data unused
                cp_async16(base + (uint32_t)j * (LDS_STRIDE * 4),
                           x + (size_t)gr * K_DIM + lane * 4);
            }
            cp_commit();
            if (pc >= 2) {                      // group pc-2 complete -> signal full
                asm volatile("cp.async.wait_group 2;");
                if (lane == 0) mbar_arrive(mb + ((pc - 2) % NBUF) * 8);
            }
            if (++buf == NBUF) { buf = 0; eph ^= 1; }
        }
        // tail flush
        if (P >= 2) {
            asm volatile("cp.async.wait_group 1;");
            if (lane == 0) mbar_arrive(mb + ((P - 2) % NBUF) * 8);
        }
        asm volatile("cp.async.wait_group 0;");
        if (lane == 0) mbar_arrive(mb + ((P - 1) % NBUF) * 8);
        return;
    }

    // ================= consumer warps (wid 0..7) =================
    const int q = lane >> 2;        // groupID (0..7)
    const int t = lane & 3;         // threadID in group (0..3)
    const int wo = wid & 3;         // o-group: cols [wo*32, wo*32+32)
    const int wm = wid >> 2;        // m-group: rows [wm*32, wm*32+32) of chunk

    // B fragments straight from gmem (L2-served, one-time), permuted k
    uint32_t Bf[16][4][2];
    #pragma unroll
    for (int s = 0; s < 16; s++) {
        const int col = 8 * s + 2 * t;
        #pragma unroll
        for (int tt = 0; tt < 4; tt++) {
            const int n = wo * 32 + tt * 8 + q;
            float2 w = *reinterpret_cast<const float2*>(W + n * K_DIM + col);
            Bf[s][tt][0] = cvt_tf32(w.x * W_SCALE);
            Bf[s][tt][1] = cvt_tf32(w.y * W_SCALE);
        }
    }

    int buf = 0, fph = 0;
    for (int c = c0; c < nchunks; c += g) {
        mbar_wait(mb + buf * 8, (uint32_t)fph);             // acquire x[c]

        const float* xb = smem + buf * BUF_FLOATS + (wm * 32 + q) * LDS_STRIDE + 2 * t;

        float acc[2][4][4];
        #pragma unroll
        for (int mt = 0; mt < 2; mt++)
            #pragma unroll
            for (int tt = 0; tt < 4; tt++)
                #pragma unroll
                for (int e = 0; e < 4; e++) acc[mt][tt][e] = 0.0f;

        // software pipeline: prefetch step s+1 A-frags while MMA-ing step s
        float2 cur[4], nxt[4];
        cur[0] = *reinterpret_cast<const float2*>(xb);
        cur[1] = *reinterpret_cast<const float2*>(xb +  8 * LDS_STRIDE);
        cur[2] = *reinterpret_cast<const float2*>(xb + 16 * LDS_STRIDE);
        cur[3] = *reinterpret_cast<const float2*>(xb + 24 * LDS_STRIDE);

        #pragma unroll
        for (int s = 0; s < 16; s++) {
            if (s < 15) {
                const float* p = xb + (s + 1) * 8;
                nxt[0] = *reinterpret_cast<const float2*>(p);
                nxt[1] = *reinterpret_cast<const float2*>(p +  8 * LDS_STRIDE);
                nxt[2] = *reinterpret_cast<const float2*>(p + 16 * LDS_STRIDE);
                nxt[3] = *reinterpret_cast<const float2*>(p + 24 * LDS_STRIDE);
            }
            #pragma unroll
            for (int mt = 0; mt < 2; mt++) {
                const uint32_t a0 = __float_as_uint(cur[2*mt    ].x);
                const uint32_t a2 = __float_as_uint(cur[2*mt    ].y);
                const uint32_t a1 = __float_as_uint(cur[2*mt + 1].x);
                const uint32_t a3 = __float_as_uint(cur[2*mt + 1].y);
                #pragma unroll
                for (int tt = 0; tt < 4; tt++) {
                    asm volatile(
                        "mma.sync.aligned.m16n8k8.row.col.f32.tf32.tf32.f32 "
                        "{%0,%1,%2,%3}, {%4,%5,%6,%7}, {%8,%9}, {%0,%1,%2,%3};"
                        : "+f"(acc[mt][tt][0]), "+f"(acc[mt][tt][1]),
                          "+f"(acc[mt][tt][2]), "+f"(acc[mt][tt][3])
                        : "r"(a0), "r"(a1), "r"(a2), "r"(a3),
                          "r"(Bf[s][tt][0]), "r"(Bf[s][tt][1]));
                }
            }
            #pragma unroll
            for (int u = 0; u < 4; u++) cur[u] = nxt[u];
        }

        // release the buffer (all LDS consumed by now: MMAs/acc depend on them)
        if (lane == 0) mbar_arrive(mb + 48 + buf * 8);

        // epilogue: 8B sector-aligned float2 stores (overlaps other warps' work)
        #pragma unroll
        for (int mt = 0; mt < 2; mt++) {
            const int r1 = c * CHUNK + wm * 32 + mt * 16 + q;
            const int r2 = r1 + 8;
            #pragma unroll
            for (int tt = 0; tt < 4; tt++) {
                const int col = wo * 32 + tt * 8 + 2 * t;
                if (r1 < nrows)
                    *reinterpret_cast<float2*>(out + (size_t)r1 * O_DIM + col) =
                        make_float2(acc[mt][tt][0], acc[mt][tt][1]);
                if (r2 < nrows)
                    *reinterpret_cast<float2*>(out + (size_t)r2 * O_DIM + col) =
                        make_float2(acc[mt][tt][2], acc[mt][tt][3]);
            }
        }

        if (++buf == NBUF) { buf = 0; fph ^= 1; }
    }
}

extern "C" void kernel_launch(void* const* d_in, const int* in_sizes, int n_in,
                              void* d_out, int out_size)
{
    const float* x = (const float*)d_in[0];
    const float* W = (const float*)d_in[1];
    float* out = (float*)d_out;

    const int nrows   = in_sizes[0] / K_DIM;
    const int nchunks = (nrows + CHUNK - 1) / CHUNK;

    cudaFuncSetAttribute(qlinear_tf32_ws,
                         cudaFuncAttributeMaxDynamicSharedMemorySize, SMEM_BYTES);

    int sms = 148;
    cudaDeviceGetAttribute(&sms, cudaDevAttrMultiProcessorCount, 0);
    int grid = sms;
    if (grid > nchunks) grid = nchunks;
    if (grid < 1) grid = 1;

    qlinear_tf32_ws<<<grid, THREADS, SMEM_BYTES>>>(x, W, out, nrows, nchunks);
}

// round 10
// speedup vs baseline: 1.2110x; 1.2110x over previous
#include <cuda_runtime.h>
#include <cstdint>

#define K_DIM      128
#define O_DIM      128
#define CHUNK      32          // rows of x per ring slot (per group)
#define THREADS    256         // 2 independent groups x 4 warps
#define GTHREADS   128         // threads per group
#define LDS_STRIDE 136         // conflict-free LDS.64 phases: banks 8q+2t distinct
#define NBUF       4           // ring depth per group (3 chunks in flight)
#define BUF_FLOATS (CHUNK * LDS_STRIDE)            // 4352
#define GROUP_FLOATS (NBUF * BUF_FLOATS)           // 17408
#define SMEM_BYTES (2 * GROUP_FLOATS * 4)          // 139264 B

// x feeds the tf32 MMA as raw fp32 bits (HW truncates to tf32).
// Mean relative shrink of truncation = 2^-11 * ln2 = 3.38e-4; compensate on W.
#define W_SCALE 1.000338f

__device__ __forceinline__ uint32_t cvt_tf32(float f) {
    uint32_t r;
    asm("cvt.rna.tf32.f32 %0, %1;" : "=r"(r) : "f"(f));
    return r;
}
__device__ __forceinline__ void cp_async16(uint32_t smem_addr, const void* gptr) {
    asm volatile("cp.async.cg.shared.global [%0], [%1], 16;" :: "r"(smem_addr), "l"(gptr));
}
__device__ __forceinline__ void cp_commit() {
    asm volatile("cp.async.commit_group;");
}
__device__ __forceinline__ void group_bar(int id) {
    asm volatile("bar.sync %0, %1;" :: "r"(id), "r"(GTHREADS) : "memory");
}

// k-permutation: MMA step s, thread t covers logical k {t, t+4}, mapped to
// physical columns {8s+2t, 8s+2t+1}. Applied to BOTH A (x, smem col) and
// B (W, gmem col) -> GEMM unchanged; A frag = one LDS.64.

__global__ void __launch_bounds__(THREADS, 1)
qlinear_tf32_2g(const float* __restrict__ x,
                const float* __restrict__ W,
                float* __restrict__ out,
                int nrows, int nchunks)
{
    extern __shared__ float smem[];
    const int tid  = threadIdx.x;
    const int lane = tid & 31;
    const int wid  = tid >> 5;
    const int gid  = wid >> 2;          // group 0/1
    const int wg   = wid & 3;           // warp within group = o-group
    const int tidg = tid & (GTHREADS - 1);

    float* gsm = smem + gid * GROUP_FLOATS;
    const uint32_t gsm_a = (uint32_t)__cvta_generic_to_shared(gsm);
    const int barid = 1 + gid;

    // this group's chunk stream: interleaved 32-row chunks
    const int c0 = blockIdx.x * 2 + gid;
    const int st = gridDim.x * 2;

    auto stage = [&](int chunk, int buf) {
        if (chunk < nchunks) {
            int row0 = chunk * CHUNK;
            uint32_t base = gsm_a + (uint32_t)(buf * BUF_FLOATS) * 4;
            #pragma unroll
            for (int j = 0; j < 8; j++) {
                int flat = tidg + j * GTHREADS;     // 0..1023 float4s
                int r  = flat >> 5;                 // 0..31
                int c4 = flat & 31;
                int gr = row0 + r;
                if (gr >= nrows) gr = nrows - 1;    // clamp: never OOB, data unused
                cp_async16(base + (uint32_t)(r * LDS_STRIDE + c4 * 4) * 4,
                           x + (size_t)gr * K_DIM + c4 * 4);
            }
        }
    };

    // start the ring: 3 chunks in flight
    stage(c0 + 0 * st, 0); cp_commit();
    stage(c0 + 1 * st, 1); cp_commit();
    stage(c0 + 2 * st, 2); cp_commit();

    // ---- per-warp geometry (within group) ----
    const int q = lane >> 2;        // groupID (0..7)
    const int t = lane & 3;         // threadID in group (0..3)
    const int wo = wg;              // o-group: cols [wo*32, wo*32+32)

    // ---- B fragments straight from gmem (L2-served, one-time), permuted k ----
    uint32_t Bf[16][4][2];
    #pragma unroll
    for (int s = 0; s < 16; s++) {
        const int col = 8 * s + 2 * t;
        #pragma unroll
        for (int tt = 0; tt < 4; tt++) {
            const int n = wo * 32 + tt * 8 + q;
            float2 w = *reinterpret_cast<const float2*>(W + n * K_DIM + col);
            Bf[s][tt][0] = cvt_tf32(w.x * W_SCALE);
            Bf[s][tt][1] = cvt_tf32(w.y * W_SCALE);
        }
    }

    // ---- main pipeline (group-local; groups never sync with each other) ----
    int idx = 0;
    for (int c = c0; c < nchunks; c += st, idx++) {
        const int buf = idx & (NBUF - 1);
        asm volatile("cp.async.wait_group 2;");     // this chunk's buffer arrived
        group_bar(barid);                           // visible to group; prev buf drained

        // restage the buffer consumed LAST iteration: safe post-barrier
        stage(c + 3 * st, (buf + 3) & (NBUF - 1));
        cp_commit();

        // thread's A base: row q, physical col 2t (warp spans all 32 chunk rows)
        const float* xb = gsm + buf * BUF_FLOATS + q * LDS_STRIDE + 2 * t;

        float acc[2][4][4];
        #pragma unroll
        for (int mt = 0; mt < 2; mt++)
            #pragma unroll
            for (int tt = 0; tt < 4; tt++)
                #pragma unroll
                for (int e = 0; e < 4; e++) acc[mt][tt][e] = 0.0f;

        // software pipeline: prefetch step s+1 A-frags while MMA-ing step s
        float2 cur[4], nxt[4];
        cur[0] = *reinterpret_cast<const float2*>(xb);                    // q      (mt0)
        cur[1] = *reinterpret_cast<const float2*>(xb +  8 * LDS_STRIDE);  // q+8    (mt0)
        cur[2] = *reinterpret_cast<const float2*>(xb + 16 * LDS_STRIDE);  // q+16   (mt1)
        cur[3] = *reinterpret_cast<const float2*>(xb + 24 * LDS_STRIDE);  // q+24   (mt1)

        #pragma unroll
        for (int s = 0; s < 16; s++) {
            if (s < 15) {
                const float* p = xb + (s + 1) * 8;
                nxt[0] = *reinterpret_cast<const float2*>(p);
                nxt[1] = *reinterpret_cast<const float2*>(p +  8 * LDS_STRIDE);
                nxt[2] = *reinterpret_cast<const float2*>(p + 16 * LDS_STRIDE);
                nxt[3] = *reinterpret_cast<const float2*>(p + 24 * LDS_STRIDE);
            }
            #pragma unroll
            for (int mt = 0; mt < 2; mt++) {
                const uint32_t a0 = __float_as_uint(cur[2*mt    ].x);
                const uint32_t a2 = __float_as_uint(cur[2*mt    ].y);
                const uint32_t a1 = __float_as_uint(cur[2*mt + 1].x);
                const uint32_t a3 = __float_as_uint(cur[2*mt + 1].y);
                #pragma unroll
                for (int tt = 0; tt < 4; tt++) {
                    asm volatile(
                        "mma.sync.aligned.m16n8k8.row.col.f32.tf32.tf32.f32 "
                        "{%0,%1,%2,%3}, {%4,%5,%6,%7}, {%8,%9}, {%0,%1,%2,%3};"
                        : "+f"(acc[mt][tt][0]), "+f"(acc[mt][tt][1]),
                          "+f"(acc[mt][tt][2]), "+f"(acc[mt][tt][3])
                        : "r"(a0), "r"(a1), "r"(a2), "r"(a3),
                          "r"(Bf[s][tt][0]), "r"(Bf[s][tt][1]));
                }
            }
            #pragma unroll
            for (int u = 0; u < 4; u++) cur[u] = nxt[u];
        }

        // ---- epilogue: 8B sector-aligned float2 stores ----
        #pragma unroll
        for (int mt = 0; mt < 2; mt++) {
            const int r1 = c * CHUNK + mt * 16 + q;
            const int r2 = r1 + 8;
            #pragma unroll
            for (int tt = 0; tt < 4; tt++) {
                const int col = wo * 32 + tt * 8 + 2 * t;
                if (r1 < nrows)
                    *reinterpret_cast<float2*>(out + (size_t)r1 * O_DIM + col) =
                        make_float2(acc[mt][tt][0], acc[mt][tt][1]);
                if (r2 < nrows)
                    *reinterpret_cast<float2*>(out + (size_t)r2 * O_DIM + col) =
                        make_float2(acc[mt][tt][2], acc[mt][tt][3]);
            }
        }
    }
}

extern "C" void kernel_launch(void* const* d_in, const int* in_sizes, int n_in,
                              void* d_out, int out_size)
{
    const float* x = (const float*)d_in[0];
    const float* W = (const float*)d_in[1];
    float* out = (float*)d_out;

    const int nrows   = in_sizes[0] / K_DIM;
    const int nchunks = (nrows + CHUNK - 1) / CHUNK;   // 32-row chunks

    cudaFuncSetAttribute(qlinear_tf32_2g,
                         cudaFuncAttributeMaxDynamicSharedMemorySize, SMEM_BYTES);

    int sms = 148;
    cudaDeviceGetAttribute(&sms, cudaDevAttrMultiProcessorCount, 0);
    int grid = sms;
    int need = (nchunks + 1) / 2;      // each CTA serves 2 chunk streams
    if (grid > need) grid = need;
    if (grid < 1) grid = 1;

    qlinear_tf32_2g<<<grid, THREADS, SMEM_BYTES>>>(x, W, out, nrows, nchunks);
}

// round 11
// speedup vs baseline: 1.2113x; 1.0003x over previous
#include <cuda_runtime.h>
#include <cstdint>

#define K_DIM      128
#define O_DIM      128
#define CHUNK      32          // rows of x per ring slot (per group)
#define THREADS    256         // 2 independent groups x 4 warps
#define GTHREADS   128         // threads per group
#define LDS_STRIDE 136         // conflict-free LDS.64 phases: banks 8q+2t distinct
#define NBUF       4           // ring depth per group (3 chunks in flight)
#define BUF_FLOATS (CHUNK * LDS_STRIDE)            // 4352
#define GROUP_FLOATS (NBUF * BUF_FLOATS)           // 17408
#define SMEM_BYTES (2 * GROUP_FLOATS * 4)          // 139264 B

// x feeds the tf32 MMA as raw fp32 bits (HW truncates to tf32).
// Mean relative shrink of truncation = 2^-11 * ln2 = 3.38e-4; compensate on W.
#define W_SCALE 1.000338f

__device__ __forceinline__ uint32_t cvt_tf32(float f) {
    uint32_t r;
    asm("cvt.rna.tf32.f32 %0, %1;" : "=r"(r) : "f"(f));
    return r;
}
__device__ __forceinline__ void cp_async16(uint32_t smem_addr, const void* gptr) {
    asm volatile("cp.async.cg.shared.global [%0], [%1], 16;" :: "r"(smem_addr), "l"(gptr));
}
__device__ __forceinline__ void cp_commit() {
    asm volatile("cp.async.commit_group;");
}
__device__ __forceinline__ void group_bar(int id) {
    asm volatile("bar.sync %0, %1;" :: "r"(id), "r"(GTHREADS) : "memory");
}

// k-permutation: MMA step s, thread t covers logical k {t, t+4}, mapped to
// physical columns {8s+2t, 8s+2t+1}. Applied to BOTH A (x, smem col) and
// B (W, gmem col) -> GEMM unchanged; A frag = one LDS.64.

__global__ void __launch_bounds__(THREADS, 1)
qlinear_tf32_2g(const float* __restrict__ x,
                const float* __restrict__ W,
                float* __restrict__ out,
                int nrows, int nchunks)
{
    extern __shared__ float smem[];
    const int tid  = threadIdx.x;
    const int lane = tid & 31;
    const int wid  = tid >> 5;
    const int gid  = wid >> 2;          // group 0/1
    const int wg   = wid & 3;           // warp within group = o-group
    const int tidg = tid & (GTHREADS - 1);

    float* gsm = smem + gid * GROUP_FLOATS;
    const uint32_t gsm_a = (uint32_t)__cvta_generic_to_shared(gsm);
    const int barid = 1 + gid;

    // this group's chunk stream: interleaved 32-row chunks
    const int c0 = blockIdx.x * 2 + gid;
    const int st = gridDim.x * 2;

    auto stage = [&](int chunk, int buf) {
        if (chunk < nchunks) {
            int row0 = chunk * CHUNK;
            uint32_t base = gsm_a + (uint32_t)(buf * BUF_FLOATS) * 4;
            #pragma unroll
            for (int j = 0; j < 8; j++) {
                int flat = tidg + j * GTHREADS;     // 0..1023 float4s
                int r  = flat >> 5;                 // 0..31
                int c4 = flat & 31;
                int gr = row0 + r;
                if (gr >= nrows) gr = nrows - 1;    // clamp: never OOB, data unused
                cp_async16(base + (uint32_t)(r * LDS_STRIDE + c4 * 4) * 4,
                           x + (size_t)gr * K_DIM + c4 * 4);
            }
        }
    };

    // start the ring: 3 chunks in flight
    stage(c0 + 0 * st, 0); cp_commit();
    stage(c0 + 1 * st, 1); cp_commit();
    stage(c0 + 2 * st, 2); cp_commit();

    // ---- per-warp geometry (within group) ----
    const int q = lane >> 2;        // groupID (0..7)
    const int t = lane & 3;         // threadID in group (0..3)
    const int wo = wg;              // o-group: cols [wo*32, wo*32+32)

    // ---- B fragments straight from gmem (L2-served, one-time), permuted k ----
    uint32_t Bf[16][4][2];
    #pragma unroll
    for (int s = 0; s < 16; s++) {
        const int col = 8 * s + 2 * t;
        #pragma unroll
        for (int tt = 0; tt < 4; tt++) {
            const int n = wo * 32 + tt * 8 + q;
            float2 w = *reinterpret_cast<const float2*>(W + n * K_DIM + col);
            Bf[s][tt][0] = cvt_tf32(w.x * W_SCALE);
            Bf[s][tt][1] = cvt_tf32(w.y * W_SCALE);
        }
    }

    // ---- main pipeline (group-local; groups never sync with each other) ----
    int idx = 0;
    for (int c = c0; c < nchunks; c += st, idx++) {
        const int buf = idx & (NBUF - 1);
        asm volatile("cp.async.wait_group 2;");     // this chunk's buffer arrived
        group_bar(barid);                           // visible to group; prev buf drained

        // restage the buffer consumed LAST iteration: safe post-barrier
        stage(c + 3 * st, (buf + 3) & (NBUF - 1));
        cp_commit();

        // thread's A base: row q, physical col 2t (warp spans all 32 chunk rows)
        const float* xb = gsm + buf * BUF_FLOATS + q * LDS_STRIDE + 2 * t;

        float acc[2][4][4];
        #pragma unroll
        for (int mt = 0; mt < 2; mt++)
            #pragma unroll
            for (int tt = 0; tt < 4; tt++)
                #pragma unroll
                for (int e = 0; e < 4; e++) acc[mt][tt][e] = 0.0f;

        // software pipeline: prefetch step s+1 A-frags while MMA-ing step s
        float2 cur[4], nxt[4];
        cur[0] = *reinterpret_cast<const float2*>(xb);                    // q      (mt0)
        cur[1] = *reinterpret_cast<const float2*>(xb +  8 * LDS_STRIDE);  // q+8    (mt0)
        cur[2] = *reinterpret_cast<const float2*>(xb + 16 * LDS_STRIDE);  // q+16   (mt1)
        cur[3] = *reinterpret_cast<const float2*>(xb + 24 * LDS_STRIDE);  // q+24   (mt1)

        #pragma unroll
        for (int s = 0; s < 16; s++) {
            if (s < 15) {
                const float* p = xb + (s + 1) * 8;
                nxt[0] = *reinterpret_cast<const float2*>(p);
                nxt[1] = *reinterpret_cast<const float2*>(p +  8 * LDS_STRIDE);
                nxt[2] = *reinterpret_cast<const float2*>(p + 16 * LDS_STRIDE);
                nxt[3] = *reinterpret_cast<const float2*>(p + 24 * LDS_STRIDE);
            }
            #pragma unroll
            for (int mt = 0; mt < 2; mt++) {
                const uint32_t a0 = __float_as_uint(cur[2*mt    ].x);
                const uint32_t a2 = __float_as_uint(cur[2*mt    ].y);
                const uint32_t a1 = __float_as_uint(cur[2*mt + 1].x);
                const uint32_t a3 = __float_as_uint(cur[2*mt + 1].y);
                #pragma unroll
                for (int tt = 0; tt < 4; tt++) {
                    asm volatile(
                        "mma.sync.aligned.m16n8k8.row.col.f32.tf32.tf32.f32 "
                        "{%0,%1,%2,%3}, {%4,%5,%6,%7}, {%8,%9}, {%0,%1,%2,%3};"
                        : "+f"(acc[mt][tt][0]), "+f"(acc[mt][tt][1]),
                          "+f"(acc[mt][tt][2]), "+f"(acc[mt][tt][3])
                        : "r"(a0), "r"(a1), "r"(a2), "r"(a3),
                          "r"(Bf[s][tt][0]), "r"(Bf[s][tt][1]));
                }
            }
            #pragma unroll
            for (int u = 0; u < 4; u++) cur[u] = nxt[u];
        }

        // ---- epilogue: 8B sector-aligned float2 stores ----
        #pragma unroll
        for (int mt = 0; mt < 2; mt++) {
            const int r1 = c * CHUNK + mt * 16 + q;
            const int r2 = r1 + 8;
            #pragma unroll
            for (int tt = 0; tt < 4; tt++) {
                const int col = wo * 32 + tt * 8 + 2 * t;
                if (r1 < nrows)
                    *reinterpret_cast<float2*>(out + (size_t)r1 * O_DIM + col) =
                        make_float2(acc[mt][tt][0], acc[mt][tt][1]);
                if (r2 < nrows)
                    *reinterpret_cast<float2*>(out + (size_t)r2 * O_DIM + col) =
                        make_float2(acc[mt][tt][2], acc[mt][tt][3]);
            }
        }
    }
}

extern "C" void kernel_launch(void* const* d_in, const int* in_sizes, int n_in,
                              void* d_out, int out_size)
{
    const float* x = (const float*)d_in[0];
    const float* W = (const float*)d_in[1];
    float* out = (float*)d_out;

    const int nrows   = in_sizes[0] / K_DIM;
    const int nchunks = (nrows + CHUNK - 1) / CHUNK;   // 32-row chunks

    cudaFuncSetAttribute(qlinear_tf32_2g,
                         cudaFuncAttributeMaxDynamicSharedMemorySize, SMEM_BYTES);

    int sms = 148;
    cudaDeviceGetAttribute(&sms, cudaDevAttrMultiProcessorCount, 0);
    int grid = sms;
    int need = (nchunks + 1) / 2;      // each CTA serves 2 chunk streams
    if (grid > need) grid = need;
    if (grid < 1) grid = 1;

    qlinear_tf32_2g<<<grid, THREADS, SMEM_BYTES>>>(x, W, out, nrows, nchunks);
}

// round 12
// speedup vs baseline: 1.2517x; 1.0334x over previous
#include <cuda_runtime.h>
#include <cstdint>

#define K_DIM      128
#define O_DIM      128
#define CHUNK      48          // rows of x per ring slot: 3 m-groups x 16 rows
#define THREADS    384         // 12 warps = 3 m-groups x 4 o-groups -> 3 warps/SMSP
#define LDS_STRIDE 136         // conflict-free LDS.64 phases: banks 8q+2t distinct
#define NBUF       6           // ring depth (5 chunks in flight)
#define BUF_FLOATS (CHUNK * LDS_STRIDE)            // 6528
#define SMEM_BYTES (NBUF * BUF_FLOATS * 4)         // 156672 B

// x feeds the tf32 MMA as raw fp32 bits (HW truncates to tf32).
// Mean relative shrink of truncation = 2^-11 * ln2 = 3.38e-4; compensate on W.
#define W_SCALE 1.000338f

__device__ __forceinline__ uint32_t cvt_tf32(float f) {
    uint32_t r;
    asm("cvt.rna.tf32.f32 %0, %1;" : "=r"(r) : "f"(f));
    return r;
}
__device__ __forceinline__ void cp_async16(uint32_t smem_addr, const void* gptr) {
    asm volatile("cp.async.cg.shared.global [%0], [%1], 16;" :: "r"(smem_addr), "l"(gptr));
}
__device__ __forceinline__ void cp_commit() {
    asm volatile("cp.async.commit_group;");
}

// k-permutation: MMA step s, thread t covers logical k {t, t+4}, mapped to
// physical columns {8s+2t, 8s+2t+1}. Applied to BOTH A (x, smem col) and
// B (W, gmem col) -> GEMM unchanged; A frag = one LDS.64.

__global__ void __launch_bounds__(THREADS, 1)
qlinear_tf32_12w(const float* __restrict__ x,
                 const float* __restrict__ W,
                 float* __restrict__ out,
                 int nrows, int nchunks)
{
    extern __shared__ float smem[];
    const int tid  = threadIdx.x;
    const int lane = tid & 31;
    const int wid  = tid >> 5;
    const uint32_t smem_a = (uint32_t)__cvta_generic_to_shared(smem);

    const int q  = lane >> 2;       // groupID (0..7)
    const int t  = lane & 3;        // threadID in group (0..3)
    const int wo = wid & 3;         // o-group: cols [wo*32, wo*32+32)
    const int wm = wid >> 2;        // m-group: rows [wm*16, wm*16+16) of chunk

    auto stage = [&](int chunk, int buf) {
        if (chunk < nchunks) {
            int row0 = chunk * CHUNK;
            uint32_t base = smem_a + (uint32_t)(buf * BUF_FLOATS) * 4;
            #pragma unroll
            for (int j = 0; j < 4; j++) {
                int flat = tid + j * THREADS;       // 0..1535 float4s
                int r  = flat >> 5;                 // 0..47
                int c4 = flat & 31;
                int gr = row0 + r;
                if (gr >= nrows) gr = nrows - 1;    // clamp: never OOB, data unused
                cp_async16(base + (uint32_t)(r * LDS_STRIDE + c4 * 4) * 4,
                           x + (size_t)gr * K_DIM + c4 * 4);
            }
        }
    };

    const int c0 = blockIdx.x;
    const int g  = gridDim.x;

    // start the ring: 5 chunks in flight
    stage(c0 + 0 * g, 0); cp_commit();
    stage(c0 + 1 * g, 1); cp_commit();
    stage(c0 + 2 * g, 2); cp_commit();
    stage(c0 + 3 * g, 3); cp_commit();
    stage(c0 + 4 * g, 4); cp_commit();

    // ---- B fragments straight from gmem (L2-served, one-time), permuted k ----
    uint32_t Bf[16][4][2];
    #pragma unroll
    for (int s = 0; s < 16; s++) {
        const int col = 8 * s + 2 * t;
        #pragma unroll
        for (int tt = 0; tt < 4; tt++) {
            const int n = wo * 32 + tt * 8 + q;
            float2 w = *reinterpret_cast<const float2*>(W + n * K_DIM + col);
            Bf[s][tt][0] = cvt_tf32(w.x * W_SCALE);
            Bf[s][tt][1] = cvt_tf32(w.y * W_SCALE);
        }
    }

    // ---- main pipeline ----
    int idx = 0;
    for (int c = c0; c < nchunks; c += g, idx++) {
        const int buf = idx % NBUF;
        asm volatile("cp.async.wait_group 4;");     // this chunk's buffer arrived
        __syncthreads();                            // visible to all; buf(idx-1) drained

        // restage the buffer consumed LAST iteration: safe post-barrier
        stage(c + 5 * g, (buf + 5) % NBUF);
        cp_commit();

        // thread's A base: row (wm*16 + q), physical col 2t
        const float* xb = smem + buf * BUF_FLOATS + (wm * 16 + q) * LDS_STRIDE + 2 * t;

        float acc[4][4];
        #pragma unroll
        for (int tt = 0; tt < 4; tt++)
            #pragma unroll
            for (int e = 0; e < 4; e++) acc[tt][e] = 0.0f;

        #pragma unroll
        for (int s = 0; s < 16; s++) {
            const float* p = xb + s * 8;
            float2 f0 = *reinterpret_cast<const float2*>(p);                   // row q
            float2 f1 = *reinterpret_cast<const float2*>(p + 8 * LDS_STRIDE);  // row q+8
            const uint32_t a0 = __float_as_uint(f0.x);
            const uint32_t a2 = __float_as_uint(f0.y);
            const uint32_t a1 = __float_as_uint(f1.x);
            const uint32_t a3 = __float_as_uint(f1.y);
            #pragma unroll
            for (int tt = 0; tt < 4; tt++) {
                asm volatile(
                    "mma.sync.aligned.m16n8k8.row.col.f32.tf32.tf32.f32 "
                    "{%0,%1,%2,%3}, {%4,%5,%6,%7}, {%8,%9}, {%0,%1,%2,%3};"
                    : "+f"(acc[tt][0]), "+f"(acc[tt][1]),
                      "+f"(acc[tt][2]), "+f"(acc[tt][3])
                    : "r"(a0), "r"(a1), "r"(a2), "r"(a3),
                      "r"(Bf[s][tt][0]), "r"(Bf[s][tt][1]));
            }
        }

        // ---- epilogue: 8B sector-aligned float2 stores ----
        const int r1 = c * CHUNK + wm * 16 + q;
        const int r2 = r1 + 8;
        #pragma unroll
        for (int tt = 0; tt < 4; tt++) {
            const int col = wo * 32 + tt * 8 + 2 * t;
            if (r1 < nrows)
                *reinterpret_cast<float2*>(out + (size_t)r1 * O_DIM + col) =
                    make_float2(acc[tt][0], acc[tt][1]);
            if (r2 < nrows)
                *reinterpret_cast<float2*>(out + (size_t)r2 * O_DIM + col) =
                    make_float2(acc[tt][2], acc[tt][3]);
        }
    }
}

extern "C" void kernel_launch(void* const* d_in, const int* in_sizes, int n_in,
                              void* d_out, int out_size)
{
    const float* x = (const float*)d_in[0];
    const float* W = (const float*)d_in[1];
    float* out = (float*)d_out;

    const int nrows   = in_sizes[0] / K_DIM;
    const int nchunks = (nrows + CHUNK - 1) / CHUNK;

    cudaFuncSetAttribute(qlinear_tf32_12w,
                         cudaFuncAttributeMaxDynamicSharedMemorySize, SMEM_BYTES);

    int sms = 148;
    cudaDeviceGetAttribute(&sms, cudaDevAttrMultiProcessorCount, 0);
    int grid = sms;
    if (grid > nchunks) grid = nchunks;
    if (grid < 1) grid = 1;

    qlinear_tf32_12w<<<grid, THREADS, SMEM_BYTES>>>(x, W, out, nrows, nchunks);
}